// round 16
// baseline (speedup 1.0000x reference)
#include <cuda_runtime.h>
#include <cuda_fp16.h>
#include <cuda_bf16.h>

// ---------------------------------------------------------------------------
// OctreeInterp R16 = R14 interp core + spatial counting-sort of points.
//  * interp is L1-gather-wavefront bound (73% L1, plateau across R11-R14).
//    Points are uniform-random (~1.9 per cell); sorting by cell key makes
//    warp-adjacent points share corner rows -> lane addresses merge within
//    each gather LDG -> distinct-row wavefronts drop ~40-50%.
//  * Counting sort on 18-bit clamped cell key ((xi&63,yi&63,zi&63) —
//    locality heuristic only, depth-agnostic). hist -> 3-kernel scan over
//    512x512 bins -> scatter (sorted pts + perm). Intra-bin order is
//    atomic-nondeterministic but per-point results depend only on that
//    point's data => output deterministic.
//  * interp reads sorted pts, writes out[perm[p]] (128B rows: store
//    wavefronts unchanged). perm==nullptr => identity (fallback path).
//  * Kept: fp16 staging, T=8 z-pair fused predicated LDG.128 gathers, half2
//    weight exchange, fp16 tree accum + xor merge, idx+1 table (no clear
//    pass), binsearch fallback for out-of-table keys (off in-bench).
// ---------------------------------------------------------------------------

#define TABLE_MAX (1 << 24)            // supports depth <= 8
__device__ int g_table[TABLE_MAX];     // idx+1 ; 0 = empty

#define MAX_DATA_ELEMS (1 << 24)       // 16M halves = 32 MB scratch
__device__ __half g_data_h[MAX_DATA_ELEMS];

#define NBINS (1 << 18)                // 512 * 512
#define CAP_PTS (1 << 20)
__device__ int    g_hist[NBINS];
__device__ int    g_scan[NBINS];
__device__ int    g_part[512];
__device__ int    g_start[NBINS];
__device__ float4 g_spts[CAP_PTS];
__device__ int    g_perm[CAP_PTS];

// ---- bin key: clamped floor-cell coords, folded to 6 bits each ----
__device__ __forceinline__ int bin_of(float4 pt, int R, float scale) {
    int xi = (int)floorf((pt.x + 1.0f) * scale - 0.5f);
    int yi = (int)floorf((pt.y + 1.0f) * scale - 0.5f);
    int zi = (int)floorf((pt.z + 1.0f) * scale - 0.5f);
    xi = min(max(xi, 0), R - 1) & 63;
    yi = min(max(yi, 0), R - 1) & 63;
    zi = min(max(zi, 0), R - 1) & 63;
    return (xi << 12) | (yi << 6) | zi;
}

// Fused prep: convert data f32->f16 (i<n8, 16B stores), table scatter
// (i<nnum), hist clear (i<NBINS).
__global__ void __launch_bounds__(256)
prep_k(const float4* __restrict__ src4, int n8,
       const int* __restrict__ keys, int nnum,
       const int* __restrict__ depth_p) {
    int i = blockIdx.x * blockDim.x + threadIdx.x;
    if (i < n8) {
        float4 a = src4[2 * i];
        float4 b = src4[2 * i + 1];
        __half2 h0 = __floats2half2_rn(a.x, a.y);
        __half2 h1 = __floats2half2_rn(a.z, a.w);
        __half2 h2 = __floats2half2_rn(b.x, b.y);
        __half2 h3 = __floats2half2_rn(b.z, b.w);
        uint4 o;
        o.x = *reinterpret_cast<unsigned*>(&h0);
        o.y = *reinterpret_cast<unsigned*>(&h1);
        o.z = *reinterpret_cast<unsigned*>(&h2);
        o.w = *reinterpret_cast<unsigned*>(&h3);
        reinterpret_cast<uint4*>(g_data_h)[i] = o;
    }
    if (i < nnum) {
        int depth = *depth_p;
        long long lim = 1LL << (3 * depth);
        if (lim > (long long)TABLE_MAX) lim = (long long)TABLE_MAX;
        int k = keys[i];
        if (k >= 0 && (long long)k < lim) g_table[k] = i + 1;   // keys unique
    }
    if (i < NBINS) g_hist[i] = 0;
}

__global__ void hist_k(const float4* __restrict__ pts4, int npts,
                       const int* __restrict__ depth_p) {
    int i = blockIdx.x * blockDim.x + threadIdx.x;
    if (i >= npts) return;
    int depth = *depth_p;
    int R = 1 << depth;
    float scale = (float)(1 << (depth - 1));
    atomicAdd(&g_hist[bin_of(pts4[i], R, scale)], 1);
}

// Block-local exclusive scan (512 bins per block, 512 blocks).
__global__ void scan1_k() {
    __shared__ int sm[512];
    int t = threadIdx.x;
    int g = blockIdx.x * 512 + t;
    int v = g_hist[g];
    sm[t] = v;
    __syncthreads();
    for (int off = 1; off < 512; off <<= 1) {
        int add = (t >= off) ? sm[t - off] : 0;
        __syncthreads();
        if (t >= off) sm[t] += add;
        __syncthreads();
    }
    int inc = sm[t];
    g_scan[g] = inc - v;                  // exclusive within block
    if (t == 511) g_part[blockIdx.x] = inc;
}

// Exclusive scan of the 512 block totals (single block).
__global__ void scan2_k() {
    __shared__ int sm[512];
    int t = threadIdx.x;
    int v = g_part[t];
    sm[t] = v;
    __syncthreads();
    for (int off = 1; off < 512; off <<= 1) {
        int add = (t >= off) ? sm[t - off] : 0;
        __syncthreads();
        if (t >= off) sm[t] += add;
        __syncthreads();
    }
    g_part[t] = sm[t] - v;                // exclusive
}

__global__ void scan3_k() {
    int i = blockIdx.x * blockDim.x + threadIdx.x;
    if (i < NBINS) g_start[i] = g_scan[i] + g_part[i >> 9];
}

__global__ void scatter_k(const float4* __restrict__ pts4, int npts,
                          const int* __restrict__ depth_p) {
    int i = blockIdx.x * blockDim.x + threadIdx.x;
    if (i >= npts) return;
    int depth = *depth_p;
    int R = 1 << depth;
    float scale = (float)(1 << (depth - 1));
    float4 pt = pts4[i];
    int pos = atomicAdd(&g_start[bin_of(pt, R, scale)], 1);
    g_spts[pos] = pt;
    g_perm[pos] = i;
}

__device__ __forceinline__ int binsearch(int key, const int* __restrict__ keys,
                                         int nnum) {
    int lo = 0, hi = nnum;
    while (lo < hi) {
        int mid = (lo + hi) >> 1;
        if (keys[mid] < key) lo = mid + 1; else hi = mid;
    }
    return (lo < nnum && keys[lo] == key) ? lo : -1;
}

__device__ __forceinline__ __half2 as_h2(unsigned u) {
    return *reinterpret_cast<__half2*>(&u);
}

// Fast path, C == 32. 256 threads = 32 points x 8 threads.
// perm != nullptr: pts4 is the sorted buffer, output row = perm[p].
__global__ void __launch_bounds__(256)
interp32z_k(const float4* __restrict__ pts4,
            const int* __restrict__ perm,
            const int* __restrict__ keys, int nnum,
            const int* __restrict__ depth_p,
            float4* __restrict__ out4, int npts) {
    int sub  = threadIdx.x & 7;
    int p    = blockIdx.x * 32 + (threadIdx.x >> 3);
    bool live = p < npts;
    int pc = min(p, npts - 1);          // tail threads compute on clamped point

    int depth = *depth_p;
    int R = 1 << depth;
    long long R3 = 1LL << (3 * depth);
    int table_lim = (int)(R3 < (long long)TABLE_MAX ? R3 : (long long)TABLE_MAX);
    float scale = (float)(1 << (depth - 1));

    float4 pt = pts4[pc];
    int op = perm ? perm[pc] : pc;      // output row (original point index)
    int b = (int)pt.w;

    float xf = (pt.x + 1.0f) * scale - 0.5f;
    float yf = (pt.y + 1.0f) * scale - 0.5f;
    float zf = (pt.z + 1.0f) * scale - 0.5f;
    float fxi = floorf(xf), fyi = floorf(yf), fzi = floorf(zf);
    int xi = (int)fxi, yi = (int)fyi, zi = (int)fzi;
    float frx = xf - fxi, fry = yf - fyi, frz = zf - fzi;

    // --- Own-corner lookup (corner id = sub; gz in bit 0) ---
    int gx = (sub >> 2) & 1, gy = (sub >> 1) & 1, gz = sub & 1;
    int cx = xi + gx, cy = yi + gy, cz = zi + gz;
    bool inb = ((unsigned)cx < (unsigned)R) &
               ((unsigned)cy < (unsigned)R) &
               ((unsigned)cz < (unsigned)R);
    float w = (gx ? frx : 1.0f - frx) *
              (gy ? fry : 1.0f - fry) *
              (gz ? frz : 1.0f - frz);
    int key = ((b * R + cx) * R + cy) * R + cz;
    int kc  = min(max(key, 0), table_lim - 1);
    int idx = __ldg(&g_table[kc]) - 1;                       // -1 if empty
    if (key >= table_lim) idx = binsearch(key, keys, nnum);  // off in-bench
    bool valid = inb & (key >= 0) & (idx >= 0);
    int   myidx = valid ? idx : -1;           // -1 sentinel gates the gather
    float myw   = valid ? w : 0.0f;
    __half2 mywh = __float2half2_rn(myw);
    unsigned mywh_u = *reinterpret_cast<unsigned*>(&mywh);

    // --- Exchange: this lane needs corners (2j + h), j = 0..3 ---
    int h = sub >> 2;                    // 0 or 1 (gz half)
    int     idxs[4];
    __half2 wh[4];
#pragma unroll
    for (int j = 0; j < 4; j++) {
        idxs[j] = __shfl_sync(0xffffffffu, myidx, 2 * j + h, 8);
        wh[j]   = as_h2(__shfl_sync(0xffffffffu, mywh_u, 2 * j + h, 8));
    }

    // wsum in f32: own weight summed across the 8-lane segment (butterfly)
    float s = myw;
    s += __shfl_xor_sync(0xffffffffu, s, 1, 8);
    s += __shfl_xor_sync(0xffffffffu, s, 2, 8);
    s += __shfl_xor_sync(0xffffffffu, s, 4, 8);
    float wsum = s;

    // --- 4 PREDICATED gathers (16B LDG.128). Sorted points make lanes of
    //     different points hit the same rows -> address merge in-flight. ---
    int cg = sub & 3;                    // 16B chunk within row
    const uint4* data_h4 = reinterpret_cast<const uint4*>(g_data_h);
    uint4 rows[4];
#pragma unroll
    for (int j = 0; j < 4; j++) {
        uint4 r = make_uint4(0u, 0u, 0u, 0u);
        if (idxs[j] >= 0)                          // @P-predicated 16B load
            r = data_h4[(size_t)((unsigned)idxs[j] * 4u + (unsigned)cg)];
        rows[j] = r;
    }

    // --- fp16 accumulation: 4 slots (8 channels) over this half's corners ---
    __half2 acc0 = __hfma2(wh[1], as_h2(rows[1].x), __hmul2(wh[0], as_h2(rows[0].x)));
    __half2 acc1 = __hfma2(wh[1], as_h2(rows[1].y), __hmul2(wh[0], as_h2(rows[0].y)));
    __half2 acc2 = __hfma2(wh[1], as_h2(rows[1].z), __hmul2(wh[0], as_h2(rows[0].z)));
    __half2 acc3 = __hfma2(wh[1], as_h2(rows[1].w), __hmul2(wh[0], as_h2(rows[0].w)));
    __half2 bcc0 = __hfma2(wh[3], as_h2(rows[3].x), __hmul2(wh[2], as_h2(rows[2].x)));
    __half2 bcc1 = __hfma2(wh[3], as_h2(rows[3].y), __hmul2(wh[2], as_h2(rows[2].y)));
    __half2 bcc2 = __hfma2(wh[3], as_h2(rows[3].z), __hmul2(wh[2], as_h2(rows[2].z)));
    __half2 bcc3 = __hfma2(wh[3], as_h2(rows[3].w), __hmul2(wh[2], as_h2(rows[2].w)));
    acc0 = __hadd2(acc0, bcc0);
    acc1 = __hadd2(acc1, bcc1);
    acc2 = __hadd2(acc2, bcc2);
    acc3 = __hadd2(acc3, bcc3);

    // --- Merge gz halves: lanes sub and sub^4 hold same channels ---
    unsigned u0 = *reinterpret_cast<unsigned*>(&acc0);
    unsigned u1 = *reinterpret_cast<unsigned*>(&acc1);
    unsigned u2 = *reinterpret_cast<unsigned*>(&acc2);
    unsigned u3 = *reinterpret_cast<unsigned*>(&acc3);
    acc0 = __hadd2(acc0, as_h2(__shfl_xor_sync(0xffffffffu, u0, 4, 8)));
    acc1 = __hadd2(acc1, as_h2(__shfl_xor_sync(0xffffffffu, u1, 4, 8)));
    acc2 = __hadd2(acc2, as_h2(__shfl_xor_sync(0xffffffffu, u2, 4, 8)));
    acc3 = __hadd2(acc3, as_h2(__shfl_xor_sync(0xffffffffu, u3, 4, 8)));

    // --- Epilogue: lane writes 4 floats of out row `op`. ---
    __half2 sa = h ? acc2 : acc0;
    __half2 sb = h ? acc3 : acc1;
    float2 fa = __half22float2(sa);
    float2 fb = __half22float2(sb);
    float inv = 1.0f / (wsum + 1e-12f);
    if (live)
        out4[(size_t)op * 8 + 2 * cg + h] =
            make_float4(fa.x * inv, fa.y * inv, fb.x * inv, fb.y * inv);
}

// Scalar f32 fallback (general C): one thread per (point, channel).
__global__ void interp_scalar_k(const float* __restrict__ data,
                                const float* __restrict__ pts,
                                const int* __restrict__ keys, int nnum,
                                const int* __restrict__ depth_p,
                                float* __restrict__ out,
                                int npts, int C) {
    long long t = (long long)blockIdx.x * blockDim.x + threadIdx.x;
    long long total = (long long)npts * C;
    if (t >= total) return;
    int p = (int)(t / C);
    int c = (int)(t % C);

    int depth = *depth_p;
    int R = 1 << depth;
    long long R3 = 1LL << (3 * depth);
    int table_lim = (int)(R3 < (long long)TABLE_MAX ? R3 : (long long)TABLE_MAX);
    float scale = (float)(1 << (depth - 1));

    const float* pp = pts + (size_t)p * 4;
    float xf = (pp[0] + 1.0f) * scale - 0.5f;
    float yf = (pp[1] + 1.0f) * scale - 0.5f;
    float zf = (pp[2] + 1.0f) * scale - 0.5f;
    int b = (int)pp[3];
    float fxi = floorf(xf), fyi = floorf(yf), fzi = floorf(zf);
    int xi = (int)fxi, yi = (int)fyi, zi = (int)fzi;
    float frx = xf - fxi, fry = yf - fyi, frz = zf - fzi;

    float acc = 0.f, wsum = 0.f;
#pragma unroll
    for (int g = 0; g < 8; g++) {
        int gx = (g >> 2) & 1, gy = (g >> 1) & 1, gz = g & 1;
        int cx = xi + gx, cy = yi + gy, cz = zi + gz;
        bool inb = (cx >= 0) & (cx < R) & (cy >= 0) & (cy < R) & (cz >= 0) & (cz < R);
        if (!inb) continue;
        int key = ((b * R + cx) * R + cy) * R + cz;
        int idx;
        if (key >= 0 && key < table_lim) idx = g_table[key] - 1;
        else idx = binsearch(key, keys, nnum);
        if (idx >= 0) {
            float w = (gx ? frx : 1.0f - frx) *
                      (gy ? fry : 1.0f - fry) *
                      (gz ? frz : 1.0f - frz);
            acc  += w * data[(size_t)idx * C + c];
            wsum += w;
        }
    }
    out[(size_t)p * C + c] = acc / (wsum + 1e-12f);
}

// Table-only build for the fallback path.
__global__ void build_table_k(const int* __restrict__ keys, int nnum,
                              const int* __restrict__ depth_p) {
    int i = blockIdx.x * blockDim.x + threadIdx.x;
    if (i >= nnum) return;
    int depth = *depth_p;
    long long lim = 1LL << (3 * depth);
    if (lim > (long long)TABLE_MAX) lim = (long long)TABLE_MAX;
    int k = keys[i];
    if (k >= 0 && (long long)k < lim) g_table[k] = i + 1;
}

extern "C" void kernel_launch(void* const* d_in, const int* in_sizes, int n_in,
                              void* d_out, int out_size) {
    const float* data      = (const float*)d_in[0];
    const float* pts       = (const float*)d_in[1];
    const int*   node_keys = (const int*)d_in[2];
    const int*   depth_p   = (const int*)d_in[3];
    float*       out       = (float*)d_out;

    int npts = in_sizes[1] / 4;
    int nnum = in_sizes[2];
    int C    = (nnum > 0) ? in_sizes[0] / nnum : 32;

    if (C == 32 && (long long)nnum * C <= (long long)MAX_DATA_ELEMS) {
        int n8 = (nnum * C) / 8;                  // uint4-of-8-halves count
        int prep_n = n8 > nnum ? n8 : nnum;
        if (prep_n < NBINS) prep_n = NBINS;
        prep_k<<<(prep_n + 255) / 256, 256>>>((const float4*)data, n8,
                                              node_keys, nnum, depth_p);

        const float4* interp_pts = (const float4*)pts;
        const int*    perm       = nullptr;
        if (npts > 0 && npts <= CAP_PTS) {
            int pb = (npts + 255) / 256;
            hist_k<<<pb, 256>>>((const float4*)pts, npts, depth_p);
            scan1_k<<<512, 512>>>();
            scan2_k<<<1, 512>>>();
            scan3_k<<<NBINS / 256, 256>>>();
            scatter_k<<<pb, 256>>>((const float4*)pts, npts, depth_p);
            // device-symbol addresses: resolve via kernel arg (no cudaGetSymbolAddress
            // needed — pass via pointers obtained below)
            cudaError_t e1 = cudaSuccess; (void)e1;
            void* spts_addr = nullptr; void* perm_addr = nullptr;
            cudaGetSymbolAddress(&spts_addr, g_spts);
            cudaGetSymbolAddress(&perm_addr, g_perm);
            interp_pts = (const float4*)spts_addr;
            perm       = (const int*)perm_addr;
        }

        int blocks = (npts + 31) / 32;            // 32 points / 256-thread block
        interp32z_k<<<blocks, 256>>>(interp_pts, perm, node_keys, nnum,
                                     depth_p, (float4*)out, npts);
    } else {
        build_table_k<<<(nnum + 255) / 256, 256>>>(node_keys, nnum, depth_p);
        long long total = (long long)npts * C;
        int blocks = (int)((total + 255) / 256);
        interp_scalar_k<<<blocks, 256>>>(data, pts, node_keys, nnum, depth_p,
                                         out, npts, C);
    }
}

// round 17
// speedup vs baseline: 1.5673x; 1.5673x over previous
#include <cuda_runtime.h>
#include <cuda_fp16.h>
#include <cuda_bf16.h>

// ---------------------------------------------------------------------------
// OctreeInterp R17 = R14b interp core (measured best: 45.06us total,
// interp 37.6us) + higher-ILP prep.
//  * R16's counting-sort experiment regressed badly (73.7us): 6 dependent
//    launches x ~3-5us graph overhead swamped any gather-locality gain.
//    Reverted; interp kernel byte-identical to R14b.
//  * Prep: each thread now converts 64B -> 32B (4x float4 in, 2x uint4 out,
//    half the threads, 2x MLP) to close the gap between prep's measured
//    7.4us and its ~4us traffic floor.
//  * Interp (unchanged): T=8, z-pair fused predicated LDG.128 fp16 gathers,
//    half2 weight exchange, butterfly wsum, fp16 tree accum + xor merge,
//    idx+1 inverse table with no clear pass, binsearch fallback for
//    out-of-table keys (off in-bench).
// ---------------------------------------------------------------------------

#define TABLE_MAX (1 << 24)            // supports depth <= 8
__device__ int g_table[TABLE_MAX];     // idx+1 ; 0 = empty

#define MAX_DATA_ELEMS (1 << 24)       // 16M halves = 32 MB scratch
__device__ __half g_data_h[MAX_DATA_ELEMS];

// Fused prep: i < n16 -> convert 4x float4 -> 2x uint4 (32B out);
//             i < nnum -> table scatter.
__global__ void __launch_bounds__(256)
prep_k(const float4* __restrict__ src4, int n16,
       const int* __restrict__ keys, int nnum,
       const int* __restrict__ depth_p) {
    int i = blockIdx.x * blockDim.x + threadIdx.x;
    if (i < n16) {
        float4 a = src4[4 * i];
        float4 b = src4[4 * i + 1];
        float4 c = src4[4 * i + 2];
        float4 d = src4[4 * i + 3];
        __half2 h0 = __floats2half2_rn(a.x, a.y);
        __half2 h1 = __floats2half2_rn(a.z, a.w);
        __half2 h2 = __floats2half2_rn(b.x, b.y);
        __half2 h3 = __floats2half2_rn(b.z, b.w);
        __half2 h4 = __floats2half2_rn(c.x, c.y);
        __half2 h5 = __floats2half2_rn(c.z, c.w);
        __half2 h6 = __floats2half2_rn(d.x, d.y);
        __half2 h7 = __floats2half2_rn(d.z, d.w);
        uint4 o0, o1;
        o0.x = *reinterpret_cast<unsigned*>(&h0);
        o0.y = *reinterpret_cast<unsigned*>(&h1);
        o0.z = *reinterpret_cast<unsigned*>(&h2);
        o0.w = *reinterpret_cast<unsigned*>(&h3);
        o1.x = *reinterpret_cast<unsigned*>(&h4);
        o1.y = *reinterpret_cast<unsigned*>(&h5);
        o1.z = *reinterpret_cast<unsigned*>(&h6);
        o1.w = *reinterpret_cast<unsigned*>(&h7);
        reinterpret_cast<uint4*>(g_data_h)[2 * i]     = o0;
        reinterpret_cast<uint4*>(g_data_h)[2 * i + 1] = o1;
    }
    if (i < nnum) {
        int depth = *depth_p;
        long long lim = 1LL << (3 * depth);
        if (lim > (long long)TABLE_MAX) lim = (long long)TABLE_MAX;
        int k = keys[i];
        if (k >= 0 && (long long)k < lim) g_table[k] = i + 1;   // keys unique
    }
}

// Tail converter for nnum*C not divisible by 16 (handles last <16 floats).
__global__ void prep_tail_k(const float* __restrict__ src, int lo, int n) {
    int i = lo + blockIdx.x * blockDim.x + threadIdx.x;
    if (i < n) g_data_h[i] = __float2half_rn(src[i]);
}

__device__ __forceinline__ int binsearch(int key, const int* __restrict__ keys,
                                         int nnum) {
    int lo = 0, hi = nnum;
    while (lo < hi) {
        int mid = (lo + hi) >> 1;
        if (keys[mid] < key) lo = mid + 1; else hi = mid;
    }
    return (lo < nnum && keys[lo] == key) ? lo : -1;
}

__device__ __forceinline__ __half2 as_h2(unsigned u) {
    return *reinterpret_cast<__half2*>(&u);
}

// Fast path, C == 32. 256 threads = 32 points x 8 threads.
// Corner numbering: c = (gx<<2)|(gy<<1)|gz ; z-pair j = c>>1.
// Lane duty: own-corner lookup for corner `sub`; gather role (j, h=sub>>2):
// loads halves [8*(sub&3), +8) of row idx(corner 2j+h).
__global__ void __launch_bounds__(256)
interp32z_k(const float4* __restrict__ pts4,
            const int* __restrict__ keys, int nnum,
            const int* __restrict__ depth_p,
            float4* __restrict__ out4, int npts) {
    int sub  = threadIdx.x & 7;
    int p    = blockIdx.x * 32 + (threadIdx.x >> 3);
    bool live = p < npts;
    int pc = min(p, npts - 1);          // tail threads compute on clamped point

    int depth = *depth_p;
    int R = 1 << depth;
    long long R3 = 1LL << (3 * depth);
    int table_lim = (int)(R3 < (long long)TABLE_MAX ? R3 : (long long)TABLE_MAX);
    float scale = (float)(1 << (depth - 1));

    float4 pt = pts4[pc];
    int b = (int)pt.w;

    float xf = (pt.x + 1.0f) * scale - 0.5f;
    float yf = (pt.y + 1.0f) * scale - 0.5f;
    float zf = (pt.z + 1.0f) * scale - 0.5f;
    float fxi = floorf(xf), fyi = floorf(yf), fzi = floorf(zf);
    int xi = (int)fxi, yi = (int)fyi, zi = (int)fzi;
    float frx = xf - fxi, fry = yf - fyi, frz = zf - fzi;

    // --- Own-corner lookup (corner id = sub; gz in bit 0) ---
    int gx = (sub >> 2) & 1, gy = (sub >> 1) & 1, gz = sub & 1;
    int cx = xi + gx, cy = yi + gy, cz = zi + gz;
    bool inb = ((unsigned)cx < (unsigned)R) &
               ((unsigned)cy < (unsigned)R) &
               ((unsigned)cz < (unsigned)R);
    float w = (gx ? frx : 1.0f - frx) *
              (gy ? fry : 1.0f - fry) *
              (gz ? frz : 1.0f - frz);
    int key = ((b * R + cx) * R + cy) * R + cz;
    int kc  = min(max(key, 0), table_lim - 1);
    int idx = __ldg(&g_table[kc]) - 1;                       // -1 if empty
    if (key >= table_lim) idx = binsearch(key, keys, nnum);  // off in-bench
    bool valid = inb & (key >= 0) & (idx >= 0);
    int   myidx = valid ? idx : -1;           // -1 sentinel gates the gather
    float myw   = valid ? w : 0.0f;
    __half2 mywh = __float2half2_rn(myw);     // one cvt per lane
    unsigned mywh_u = *reinterpret_cast<unsigned*>(&mywh);

    // --- Exchange: this lane needs corners (2j + h), j = 0..3 ---
    int h = sub >> 2;                    // 0 or 1 (gz half)
    int     idxs[4];
    __half2 wh[4];
#pragma unroll
    for (int j = 0; j < 4; j++) {
        idxs[j] = __shfl_sync(0xffffffffu, myidx, 2 * j + h, 8);
        wh[j]   = as_h2(__shfl_sync(0xffffffffu, mywh_u, 2 * j + h, 8));
    }

    // wsum in f32: own weight summed across the 8-lane segment (butterfly)
    float s = myw;
    s += __shfl_xor_sync(0xffffffffu, s, 1, 8);
    s += __shfl_xor_sync(0xffffffffu, s, 2, 8);
    s += __shfl_xor_sync(0xffffffffu, s, 4, 8);
    float wsum = s;

    // --- 4 PREDICATED gathers (16B LDG.128). For pair j, lanes 0-3 cover
    //     row i0, lanes 4-7 row i1 -> one 128B line when indices adjacent.
    //     ~24% invalid corners skip their load (L1 is the binder). ---
    int cg = sub & 3;                    // 16B chunk within row
    const uint4* data_h4 = reinterpret_cast<const uint4*>(g_data_h);
    uint4 rows[4];
#pragma unroll
    for (int j = 0; j < 4; j++) {
        uint4 r = make_uint4(0u, 0u, 0u, 0u);
        if (idxs[j] >= 0)                          // @P-predicated 16B load
            r = data_h4[(size_t)((unsigned)idxs[j] * 4u + (unsigned)cg)];
        rows[j] = r;
    }

    // --- fp16 accumulation: 4 slots (8 channels) over this half's corners ---
    __half2 acc0 = __hfma2(wh[1], as_h2(rows[1].x), __hmul2(wh[0], as_h2(rows[0].x)));
    __half2 acc1 = __hfma2(wh[1], as_h2(rows[1].y), __hmul2(wh[0], as_h2(rows[0].y)));
    __half2 acc2 = __hfma2(wh[1], as_h2(rows[1].z), __hmul2(wh[0], as_h2(rows[0].z)));
    __half2 acc3 = __hfma2(wh[1], as_h2(rows[1].w), __hmul2(wh[0], as_h2(rows[0].w)));
    __half2 bcc0 = __hfma2(wh[3], as_h2(rows[3].x), __hmul2(wh[2], as_h2(rows[2].x)));
    __half2 bcc1 = __hfma2(wh[3], as_h2(rows[3].y), __hmul2(wh[2], as_h2(rows[2].y)));
    __half2 bcc2 = __hfma2(wh[3], as_h2(rows[3].z), __hmul2(wh[2], as_h2(rows[2].z)));
    __half2 bcc3 = __hfma2(wh[3], as_h2(rows[3].w), __hmul2(wh[2], as_h2(rows[2].w)));
    acc0 = __hadd2(acc0, bcc0);
    acc1 = __hadd2(acc1, bcc1);
    acc2 = __hadd2(acc2, bcc2);
    acc3 = __hadd2(acc3, bcc3);

    // --- Merge gz halves: lanes sub and sub^4 hold same channels ---
    unsigned u0 = *reinterpret_cast<unsigned*>(&acc0);
    unsigned u1 = *reinterpret_cast<unsigned*>(&acc1);
    unsigned u2 = *reinterpret_cast<unsigned*>(&acc2);
    unsigned u3 = *reinterpret_cast<unsigned*>(&acc3);
    acc0 = __hadd2(acc0, as_h2(__shfl_xor_sync(0xffffffffu, u0, 4, 8)));
    acc1 = __hadd2(acc1, as_h2(__shfl_xor_sync(0xffffffffu, u1, 4, 8)));
    acc2 = __hadd2(acc2, as_h2(__shfl_xor_sync(0xffffffffu, u2, 4, 8)));
    acc3 = __hadd2(acc3, as_h2(__shfl_xor_sync(0xffffffffu, u3, 4, 8)));

    // --- Epilogue: lane writes 4 floats. h=0 -> slots 0,1 ; h=1 -> slots 2,3.
    //     out float4 index = p*8 + 2*cg + h ---
    __half2 sa = h ? acc2 : acc0;
    __half2 sb = h ? acc3 : acc1;
    float2 fa = __half22float2(sa);
    float2 fb = __half22float2(sb);
    float inv = 1.0f / (wsum + 1e-12f);
    if (live)
        out4[(size_t)p * 8 + 2 * cg + h] =
            make_float4(fa.x * inv, fa.y * inv, fb.x * inv, fb.y * inv);
}

// Scalar f32 fallback (general C): one thread per (point, channel).
__global__ void interp_scalar_k(const float* __restrict__ data,
                                const float* __restrict__ pts,
                                const int* __restrict__ keys, int nnum,
                                const int* __restrict__ depth_p,
                                float* __restrict__ out,
                                int npts, int C) {
    long long t = (long long)blockIdx.x * blockDim.x + threadIdx.x;
    long long total = (long long)npts * C;
    if (t >= total) return;
    int p = (int)(t / C);
    int c = (int)(t % C);

    int depth = *depth_p;
    int R = 1 << depth;
    long long R3 = 1LL << (3 * depth);
    int table_lim = (int)(R3 < (long long)TABLE_MAX ? R3 : (long long)TABLE_MAX);
    float scale = (float)(1 << (depth - 1));

    const float* pp = pts + (size_t)p * 4;
    float xf = (pp[0] + 1.0f) * scale - 0.5f;
    float yf = (pp[1] + 1.0f) * scale - 0.5f;
    float zf = (pp[2] + 1.0f) * scale - 0.5f;
    int b = (int)pp[3];
    float fxi = floorf(xf), fyi = floorf(yf), fzi = floorf(zf);
    int xi = (int)fxi, yi = (int)fyi, zi = (int)fzi;
    float frx = xf - fxi, fry = yf - fyi, frz = zf - fzi;

    float acc = 0.f, wsum = 0.f;
#pragma unroll
    for (int g = 0; g < 8; g++) {
        int gx = (g >> 2) & 1, gy = (g >> 1) & 1, gz = g & 1;
        int cx = xi + gx, cy = yi + gy, cz = zi + gz;
        bool inb = (cx >= 0) & (cx < R) & (cy >= 0) & (cy < R) & (cz >= 0) & (cz < R);
        if (!inb) continue;
        int key = ((b * R + cx) * R + cy) * R + cz;
        int idx;
        if (key >= 0 && key < table_lim) idx = g_table[key] - 1;
        else idx = binsearch(key, keys, nnum);
        if (idx >= 0) {
            float w = (gx ? frx : 1.0f - frx) *
                      (gy ? fry : 1.0f - fry) *
                      (gz ? frz : 1.0f - frz);
            acc  += w * data[(size_t)idx * C + c];
            wsum += w;
        }
    }
    out[(size_t)p * C + c] = acc / (wsum + 1e-12f);
}

// Table-only build for the fallback path.
__global__ void build_table_k(const int* __restrict__ keys, int nnum,
                              const int* __restrict__ depth_p) {
    int i = blockIdx.x * blockDim.x + threadIdx.x;
    if (i >= nnum) return;
    int depth = *depth_p;
    long long lim = 1LL << (3 * depth);
    if (lim > (long long)TABLE_MAX) lim = (long long)TABLE_MAX;
    int k = keys[i];
    if (k >= 0 && (long long)k < lim) g_table[k] = i + 1;
}

extern "C" void kernel_launch(void* const* d_in, const int* in_sizes, int n_in,
                              void* d_out, int out_size) {
    const float* data      = (const float*)d_in[0];
    const float* pts       = (const float*)d_in[1];
    const int*   node_keys = (const int*)d_in[2];
    const int*   depth_p   = (const int*)d_in[3];
    float*       out       = (float*)d_out;

    int npts = in_sizes[1] / 4;
    int nnum = in_sizes[2];
    int C    = (nnum > 0) ? in_sizes[0] / nnum : 32;

    if (C == 32 && (long long)nnum * C <= (long long)MAX_DATA_ELEMS) {
        int total_elems = nnum * C;
        int n16 = total_elems / 16;               // 64B-in / 32B-out chunks
        int prep_n = n16 > nnum ? n16 : nnum;
        prep_k<<<(prep_n + 255) / 256, 256>>>((const float4*)data, n16,
                                              node_keys, nnum, depth_p);
        int tail_lo = n16 * 16;
        if (tail_lo < total_elems) {
            int tail_n = total_elems - tail_lo;   // < 16 elements
            prep_tail_k<<<1, 32>>>(data, tail_lo, total_elems);
            (void)tail_n;
        }
        int blocks = (npts + 31) / 32;            // 32 points / 256-thread block
        interp32z_k<<<blocks, 256>>>((const float4*)pts, node_keys, nnum,
                                     depth_p, (float4*)out, npts);
    } else {
        build_table_k<<<(nnum + 255) / 256, 256>>>(node_keys, nnum, depth_p);
        long long total = (long long)npts * C;
        int blocks = (int)((total + 255) / 256);
        interp_scalar_k<<<blocks, 256>>>(data, pts, node_keys, nnum, depth_p,
                                         out, npts, C);
    }
}